// round 8
// baseline (speedup 1.0000x reference)
#include <cuda_runtime.h>

// Spline1DInterpolant, compact-support closed form. FINAL form.
//
// s = (x-a)*n/(b-a); ib = floor(s); f = s-ib in [0,1); g = 1-f.
// y = c[ib]*g^3 + c[ib+1]*(4-6f^2+3f^3) + c[ib+2]*(4-6g^2+3g^3) + c[ib+3]*f^3
// (all other basis terms are exactly 0: compact support t<2)
//
// The 4 coeffs are consecutive -> fetch 2 aligned float4 blocks, select the
// window [r..r+3], r = ib&3, with SELs. Edge clamp of the second block only
// aliases positions whose weight is exactly 0 (s == n).
//
// Status: launch-overhead bound. Across 5 structurally different variants
// (scalar/float4, branched/branch-free, 32-256 CTA grids) chip time is pinned
// at 5.1-5.3us with DRAM=0.2% and all pipes <2% -- the ~90KB working set and
// ~600-cycle latency chain are fully hidden under the per-launch floor.
// Grid 128x128 spreads the single wave across ~128 SMs for minimal drain.

__global__ __launch_bounds__(128, 1)
void spline1d_kernel(const float* __restrict__ x,
                     const float* __restrict__ a,
                     const float* __restrict__ b,
                     const float* __restrict__ n,
                     const float4* __restrict__ c4,
                     float* __restrict__ out,
                     int B, int C4) {
    int tid = blockIdx.x * blockDim.x + threadIdx.x;
    if (tid >= B) return;

    float av = a[0];
    float inv_h = n[0] / (b[0] - av);
    float s = (x[tid] - av) * inv_h;        // s in [0, n], n = 4*C4 - 3

    int ib = __float2int_rd(s);             // floor; s >= 0 -> ib >= 0
    float f = s - (float)ib;                // [0,1)
    float g = 1.0f - f;

    float f2 = f * f, f3 = f2 * f;
    float g2 = g * g, g3 = g2 * g;

    float w0 = g3;
    float w1 = fmaf(3.0f, f3, fmaf(-6.0f, f2, 4.0f));
    float w2 = fmaf(3.0f, g3, fmaf(-6.0f, g2, 4.0f));
    float w3 = f3;

    int base  = ib >> 2;                    // 0 .. C4-1
    int r     = ib & 3;
    int base1 = min(base + 1, C4 - 1);      // aliased lanes carry weight 0

    float4 q0 = c4[base];
    float4 q1 = c4[base1];

    float d0 = (r == 0) ? q0.x : (r == 1) ? q0.y : (r == 2) ? q0.z : q0.w;
    float d1 = (r == 0) ? q0.y : (r == 1) ? q0.z : (r == 2) ? q0.w : q1.x;
    float d2 = (r == 0) ? q0.z : (r == 1) ? q0.w : (r == 2) ? q1.x : q1.y;
    float d3 = (r == 0) ? q0.w : (r == 1) ? q1.x : (r == 2) ? q1.y : q1.z;

    float acc = d0 * w0;
    acc = fmaf(d1, w1, acc);
    acc = fmaf(d2, w2, acc);
    acc = fmaf(d3, w3, acc);
    out[tid] = acc;
}

extern "C" void kernel_launch(void* const* d_in, const int* in_sizes, int n_in,
                              void* d_out, int out_size) {
    const float* x = (const float*)d_in[0];
    const float* a = (const float*)d_in[1];
    const float* b = (const float*)d_in[2];
    const float* n = (const float*)d_in[3];
    const float* c = (const float*)d_in[4];
    float* out = (float*)d_out;

    int B = in_sizes[0];      // 16384
    int C = in_sizes[4];      // 4096 (divisible by 4)

    int threads = 128;
    int blocks = (B + threads - 1) / threads;   // 128 CTAs -> ~1 per SM, 1 wave
    spline1d_kernel<<<blocks, threads>>>(x, a, b, n, (const float4*)c,
                                         out, B, C >> 2);
}

// round 9
// speedup vs baseline: 1.0337x; 1.0337x over previous
#include <cuda_runtime.h>

// Spline1DInterpolant, compact-support closed form. FINAL.
//
// s = (x-a)*n/(b-a); ib = floor(s); f = s-ib in [0,1); g = 1-f.
// y = c[ib]*g^3 + c[ib+1]*(4-6f^2+3f^3) + c[ib+2]*(4-6g^2+3g^3) + c[ib+3]*f^3
// (all other basis terms are exactly 0: compact support t<2)
//
// Gather: the 4 coeffs are consecutive -> fetch 2 aligned float4 blocks and
// select window [r..r+3], r = ib&3, with SELs (2 LDGs instead of 4 scattered).
// Edge clamp of the second block only aliases positions whose weight is
// exactly 0 (s == n).
//
// Status: launch-overhead bound. Six structurally different variants
// (scalar/float4, branched/branch-free, 32-256 CTA grids) all pin chip time
// at 4.99-5.34us with DRAM=0.2%, issue ~2-6%, all pipes <2%. True critical
// path is ~900 cycles (~0.8us); the rest is fixed per-launch cost. This is
// the floor; grid 128x128 covers B exactly (no tail guard) on ~128 SMs in
// one wave.

__global__ __launch_bounds__(128, 1)
void spline1d_kernel(const float* __restrict__ x,
                     const float* __restrict__ a,
                     const float* __restrict__ b,
                     const float* __restrict__ n,
                     const float4* __restrict__ c4,
                     float* __restrict__ out,
                     int C4) {
    int tid = blockIdx.x * blockDim.x + threadIdx.x;   // grid covers B exactly

    float av = a[0];
    float inv_h = n[0] / (b[0] - av);
    float s = (x[tid] - av) * inv_h;        // s in [0, n], n = 4*C4 - 3

    int ib = __float2int_rd(s);             // floor; s >= 0 -> ib >= 0
    float f = s - (float)ib;                // [0,1)
    float g = 1.0f - f;

    float f2 = f * f, f3 = f2 * f;
    float g2 = g * g, g3 = g2 * g;

    float w0 = g3;
    float w1 = fmaf(3.0f, f3, fmaf(-6.0f, f2, 4.0f));
    float w2 = fmaf(3.0f, g3, fmaf(-6.0f, g2, 4.0f));
    float w3 = f3;

    int base  = ib >> 2;                    // 0 .. C4-1
    int r     = ib & 3;
    int base1 = min(base + 1, C4 - 1);      // aliased lanes carry weight 0

    float4 q0 = c4[base];
    float4 q1 = c4[base1];

    float d0 = (r == 0) ? q0.x : (r == 1) ? q0.y : (r == 2) ? q0.z : q0.w;
    float d1 = (r == 0) ? q0.y : (r == 1) ? q0.z : (r == 2) ? q0.w : q1.x;
    float d2 = (r == 0) ? q0.z : (r == 1) ? q0.w : (r == 2) ? q1.x : q1.y;
    float d3 = (r == 0) ? q0.w : (r == 1) ? q1.x : (r == 2) ? q1.y : q1.z;

    float acc = d0 * w0;
    acc = fmaf(d1, w1, acc);
    acc = fmaf(d2, w2, acc);
    acc = fmaf(d3, w3, acc);
    out[tid] = acc;
}

// Fallback with tail guard for shapes not divisible by the block size.
__global__ __launch_bounds__(128, 1)
void spline1d_kernel_guarded(const float* __restrict__ x,
                             const float* __restrict__ a,
                             const float* __restrict__ b,
                             const float* __restrict__ n,
                             const float4* __restrict__ c4,
                             float* __restrict__ out,
                             int B, int C4) {
    int tid = blockIdx.x * blockDim.x + threadIdx.x;
    if (tid >= B) return;

    float av = a[0];
    float inv_h = n[0] / (b[0] - av);
    float s = (x[tid] - av) * inv_h;

    int ib = __float2int_rd(s);
    float f = s - (float)ib;
    float g = 1.0f - f;

    float f2 = f * f, f3 = f2 * f;
    float g2 = g * g, g3 = g2 * g;

    float w0 = g3;
    float w1 = fmaf(3.0f, f3, fmaf(-6.0f, f2, 4.0f));
    float w2 = fmaf(3.0f, g3, fmaf(-6.0f, g2, 4.0f));
    float w3 = f3;

    int base  = ib >> 2;
    int r     = ib & 3;
    int base1 = min(base + 1, C4 - 1);

    float4 q0 = c4[base];
    float4 q1 = c4[base1];

    float d0 = (r == 0) ? q0.x : (r == 1) ? q0.y : (r == 2) ? q0.z : q0.w;
    float d1 = (r == 0) ? q0.y : (r == 1) ? q0.z : (r == 2) ? q0.w : q1.x;
    float d2 = (r == 0) ? q0.z : (r == 1) ? q0.w : (r == 2) ? q1.x : q1.y;
    float d3 = (r == 0) ? q0.w : (r == 1) ? q1.x : (r == 2) ? q1.y : q1.z;

    float acc = d0 * w0;
    acc = fmaf(d1, w1, acc);
    acc = fmaf(d2, w2, acc);
    acc = fmaf(d3, w3, acc);
    out[tid] = acc;
}

extern "C" void kernel_launch(void* const* d_in, const int* in_sizes, int n_in,
                              void* d_out, int out_size) {
    const float* x = (const float*)d_in[0];
    const float* a = (const float*)d_in[1];
    const float* b = (const float*)d_in[2];
    const float* n = (const float*)d_in[3];
    const float* c = (const float*)d_in[4];
    float* out = (float*)d_out;

    int B = in_sizes[0];      // 16384
    int C = in_sizes[4];      // 4096 (divisible by 4)

    const int threads = 128;
    if ((B % threads) == 0) {
        spline1d_kernel<<<B / threads, threads>>>(x, a, b, n, (const float4*)c,
                                                  out, C >> 2);
    } else {
        spline1d_kernel_guarded<<<(B + threads - 1) / threads, threads>>>(
            x, a, b, n, (const float4*)c, out, B, C >> 2);
    }
}

// round 10
// speedup vs baseline: 1.0386x; 1.0048x over previous
#include <cuda_runtime.h>

// Spline1DInterpolant, compact-support closed form. FINAL (committed).
//
// Math: s = (x-a)*n/(b-a); ib = floor(s); f = s-ib in [0,1); g = 1-f.
//   y = c[ib]*g^3 + c[ib+1]*(4-6f^2+3f^3) + c[ib+2]*(4-6g^2+3g^3) + c[ib+3]*f^3
// All other basis terms are exactly 0 (compact support t<2), so the dense
// [B,4096] matvec in the reference collapses to 4 taps per query.
//
// Gather: the 4 coeffs are consecutive -> fetch 2 aligned float4 blocks and
// select window [r..r+3], r = ib&3, with SELs (2 LDGs instead of 4 scattered).
// Edge clamp of the second block only aliases positions whose weight is
// exactly 0 (s == n boundary).
//
// Perf conclusion (7 variants, rounds 1-9): launch-overhead bound. Chip time
// pinned 4.99-5.34us regardless of structure; DRAM 0.2%, issue ~2%, all
// pipes <2%. True critical path ~900 cycles (~0.8us); remainder is fixed
// per-launch + graph-replay cost. 128 CTAs x 128 threads = 1 wave across
// ~128 SMs, exact grid (no tail guard needed for B=16384).

__global__ __launch_bounds__(128, 1)
void spline1d_kernel(const float* __restrict__ x,
                     const float* __restrict__ a,
                     const float* __restrict__ b,
                     const float* __restrict__ n,
                     const float4* __restrict__ c4,
                     float* __restrict__ out,
                     int C4) {
    int tid = blockIdx.x * blockDim.x + threadIdx.x;   // grid covers B exactly

    // Unique per-thread load first: start the longest latency chain at issue 0.
    float xv = __ldg(&x[tid]);
    float av = __ldg(&a[0]);
    float bv = __ldg(&b[0]);
    float nv = __ldg(&n[0]);

    float inv_h = nv / (bv - av);
    float s = (xv - av) * inv_h;            // s in [0, n], n = 4*C4 - 3

    int ib = __float2int_rd(s);             // floor; s >= 0 -> ib >= 0
    float f = s - (float)ib;                // [0,1)
    float g = 1.0f - f;

    float f2 = f * f, f3 = f2 * f;
    float g2 = g * g, g3 = g2 * g;

    float w0 = g3;
    float w1 = fmaf(3.0f, f3, fmaf(-6.0f, f2, 4.0f));
    float w2 = fmaf(3.0f, g3, fmaf(-6.0f, g2, 4.0f));
    float w3 = f3;

    int base  = ib >> 2;                    // 0 .. C4-1
    int r     = ib & 3;
    int base1 = min(base + 1, C4 - 1);      // aliased lanes carry weight 0

    float4 q0 = c4[base];
    float4 q1 = c4[base1];

    float d0 = (r == 0) ? q0.x : (r == 1) ? q0.y : (r == 2) ? q0.z : q0.w;
    float d1 = (r == 0) ? q0.y : (r == 1) ? q0.z : (r == 2) ? q0.w : q1.x;
    float d2 = (r == 0) ? q0.z : (r == 1) ? q0.w : (r == 2) ? q1.x : q1.y;
    float d3 = (r == 0) ? q0.w : (r == 1) ? q1.x : (r == 2) ? q1.y : q1.z;

    float acc = d0 * w0;
    acc = fmaf(d1, w1, acc);
    acc = fmaf(d2, w2, acc);
    acc = fmaf(d3, w3, acc);
    out[tid] = acc;
}

// Fallback with tail guard for shapes not divisible by the block size.
__global__ __launch_bounds__(128, 1)
void spline1d_kernel_guarded(const float* __restrict__ x,
                             const float* __restrict__ a,
                             const float* __restrict__ b,
                             const float* __restrict__ n,
                             const float4* __restrict__ c4,
                             float* __restrict__ out,
                             int B, int C4) {
    int tid = blockIdx.x * blockDim.x + threadIdx.x;
    if (tid >= B) return;

    float xv = __ldg(&x[tid]);
    float av = __ldg(&a[0]);
    float bv = __ldg(&b[0]);
    float nv = __ldg(&n[0]);

    float inv_h = nv / (bv - av);
    float s = (xv - av) * inv_h;

    int ib = __float2int_rd(s);
    float f = s - (float)ib;
    float g = 1.0f - f;

    float f2 = f * f, f3 = f2 * f;
    float g2 = g * g, g3 = g2 * g;

    float w0 = g3;
    float w1 = fmaf(3.0f, f3, fmaf(-6.0f, f2, 4.0f));
    float w2 = fmaf(3.0f, g3, fmaf(-6.0f, g2, 4.0f));
    float w3 = f3;

    int base  = ib >> 2;
    int r     = ib & 3;
    int base1 = min(base + 1, C4 - 1);

    float4 q0 = c4[base];
    float4 q1 = c4[base1];

    float d0 = (r == 0) ? q0.x : (r == 1) ? q0.y : (r == 2) ? q0.z : q0.w;
    float d1 = (r == 0) ? q0.y : (r == 1) ? q0.z : (r == 2) ? q0.w : q1.x;
    float d2 = (r == 0) ? q0.z : (r == 1) ? q0.w : (r == 2) ? q1.x : q1.y;
    float d3 = (r == 0) ? q0.w : (r == 1) ? q1.x : (r == 2) ? q1.y : q1.z;

    float acc = d0 * w0;
    acc = fmaf(d1, w1, acc);
    acc = fmaf(d2, w2, acc);
    acc = fmaf(d3, w3, acc);
    out[tid] = acc;
}

extern "C" void kernel_launch(void* const* d_in, const int* in_sizes, int n_in,
                              void* d_out, int out_size) {
    const float* x = (const float*)d_in[0];
    const float* a = (const float*)d_in[1];
    const float* b = (const float*)d_in[2];
    const float* n = (const float*)d_in[3];
    const float* c = (const float*)d_in[4];
    float* out = (float*)d_out;

    int B = in_sizes[0];      // 16384
    int C = in_sizes[4];      // 4096 (divisible by 4)

    const int threads = 128;
    if ((B % threads) == 0) {
        spline1d_kernel<<<B / threads, threads>>>(x, a, b, n, (const float4*)c,
                                                  out, C >> 2);
    } else {
        spline1d_kernel_guarded<<<(B + threads - 1) / threads, threads>>>(
            x, a, b, n, (const float4*)c, out, B, C >> 2);
    }
}